// round 7
// baseline (speedup 1.0000x reference)
#include <cuda_runtime.h>
#include <cuda_bf16.h>
#include <cstdint>

// HONU order-2: out[i] = sum_{j<=k} W[p(j,k)] x[i,j] x[i,k] + b
// Reformulated: acc_k = sum_j x_j A[j][k] (A zero-filled full square),
// out = sum_k acc_k x_k + b.
// Warp = 8 rows x 4 k-lanes; lane t owns interleaved 16B chunks {t,t+4,t+8,t+12}
// (consecutive quads per load -> conflict-free). x row in registers (loaded
// once), A row broadcast across row-lanes, packed f32x2 math, single kernel.

#define AST 68                  // padded A/xs row stride in floats
#define RPB 32                  // rows per 128-thread CTA
#define THREADS 128

__device__ __forceinline__ void lds_v2u64(uint64_t& a, uint64_t& b, unsigned addr) {
    asm volatile("ld.shared.v2.b64 {%0,%1}, [%2];" : "=l"(a), "=l"(b) : "r"(addr));
}
__device__ __forceinline__ void fma2(uint64_t& d, uint64_t a, uint64_t b) {
    asm volatile("fma.rn.f32x2 %0, %1, %2, %0;" : "+l"(d) : "l"(a), "l"(b));
}

__global__ void __launch_bounds__(THREADS) honu_kernel(
    const float* __restrict__ x, const float* __restrict__ W,
    const float* __restrict__ bias, float* __restrict__ out)
{
    __shared__ __align__(16) float A[64 * AST];    // 17.4 KB, zero-filled square
    __shared__ __align__(16) float xs[RPB * AST];  //  8.7 KB

    const int tid  = threadIdx.x;
    const int row0 = blockIdx.x * RPB;

    // --- Expand packed W into A (each thread fills half of one row)
    {
        const int j   = tid & 63;
        const int h   = tid >> 6;
        const int off = j * 64 - ((j * (j - 1)) >> 1) - j;   // W[off+k] valid k>=j
        const int k0  = h * 34;
        #pragma unroll
        for (int kk = 0; kk < 34; ++kk) {
            int k = k0 + kk;
            float v = 0.0f;
            if (k >= j && k < 64) v = W[off + k];
            A[j * AST + k] = v;
        }
    }
    // --- Stage 32x64 x tile (coalesced float4, stride 17 float4s)
    {
        const float4* xg4 = reinterpret_cast<const float4*>(x + (size_t)row0 * 64);
        float4*       xs4 = reinterpret_cast<float4*>(xs);
        #pragma unroll
        for (int it = 0; it < 4; ++it) {
            int i = it * THREADS + tid;     // 0..511
            int r = i >> 4, c = i & 15;
            xs4[r * 17 + c] = xg4[i];
        }
    }
    __syncthreads();

    const int lane = tid & 31;
    const int t    = lane & 3;                       // k-chunk lane
    const int r    = ((tid >> 5) << 3) + (lane >> 2); // local row 0..31

    // --- Preload this lane's 16 x values (chunks t, t+4, t+8, t+12) as 8 packs
    uint64_t xp[8];
    {
        const float4* xs4 = reinterpret_cast<const float4*>(xs);
        #pragma unroll
        for (int i = 0; i < 4; ++i) {
            float4 v = xs4[r * 17 + t + 4 * i];
            asm volatile("mov.b64 %0, {%1,%2};" : "=l"(xp[2 * i])
                         : "r"(__float_as_uint(v.x)), "r"(__float_as_uint(v.y)));
            asm volatile("mov.b64 %0, {%1,%2};" : "=l"(xp[2 * i + 1])
                         : "r"(__float_as_uint(v.z)), "r"(__float_as_uint(v.w)));
        }
    }

    const unsigned Ab = (unsigned)__cvta_generic_to_shared(A) + t * 16;
    const unsigned xb = (unsigned)__cvta_generic_to_shared(xs) + r * (AST * 4);

    // --- Main loop: acc_k += x_j * A[j][k]  (immediate-offset LDS, full unroll)
    uint64_t acc[8] = {0, 0, 0, 0, 0, 0, 0, 0};
    #pragma unroll
    for (int j = 0; j < 64; ++j) {
        uint32_t xj;
        asm volatile("ld.shared.b32 %0, [%1];" : "=r"(xj) : "r"(xb + j * 4));
        uint64_t xj2;
        asm volatile("mov.b64 %0, {%1,%1};" : "=l"(xj2) : "r"(xj));
        #pragma unroll
        for (int i = 0; i < 4; ++i) {
            uint64_t a0, a1;
            lds_v2u64(a0, a1, Ab + j * (AST * 4) + i * 64);  // quads t..t+3: CF
            fma2(acc[2 * i],     a0, xj2);
            fma2(acc[2 * i + 1], a1, xj2);
        }
    }

    // --- Epilogue: res = sum_k acc_k x_k (packed), unpack, reduce 4 t-lanes
    uint64_t res = 0;
    #pragma unroll
    for (int p = 0; p < 8; ++p) fma2(res, acc[p], xp[p]);

    uint32_t lo, hi;
    asm volatile("mov.b64 {%0,%1}, %2;" : "=r"(lo), "=r"(hi) : "l"(res));
    float a = __uint_as_float(lo) + __uint_as_float(hi);
    a += __shfl_xor_sync(0xffffffffu, a, 1);
    a += __shfl_xor_sync(0xffffffffu, a, 2);

    if (t == 0) out[row0 + r] = a + bias[0];
}

extern "C" void kernel_launch(void* const* d_in, const int* in_sizes, int n_in,
                              void* d_out, int out_size) {
    const float* x = (const float*)d_in[0];   // (16384, 64) f32
    const float* W = (const float*)d_in[1];   // (2145,)  f32 (first 2080 used)
    const float* b = (const float*)d_in[2];   // (1,)     f32
    float*     out = (float*)d_out;           // (16384,) f32

    const int blocks = out_size / RPB;        // 512
    honu_kernel<<<blocks, THREADS>>>(x, W, b, out);
}